// round 11
// baseline (speedup 1.0000x reference)
#include <cuda_runtime.h>
#include <cuda_bf16.h>
#include <cstdint>

// Embedding gather: out[i, :] = embeddings[x[i], :]
// x: int32 [8192], embeddings: fp32 [32000, 1024], out: fp32 [8192, 1024]
//
// Final kernel (re-bench; previous round died on container infra, kernel
// never ran). Session conclusion: the op is bound by the chip-level LTS
// (L2 crossbar) service cap, which is path-independent (LDG == TMA == hybrid,
// all measured equal) and insensitive to occupancy/MLP/cache policy. Combined
// mandatory LTS traffic is 64MB (32MB gathered reads + 32MB writes); at the
// measured 10.5us we run at ~90% of the ~6300 B/cyc LTS ceiling.
//
// Config = best of 8 measured variants (10.528us):
//   1024 CTAs x 256 threads, 8 rows/CTA, front-batched MLP=8,
//   ld.global.cg gathers (skip L1), st.global.cs stores (evict-first).
// Micro-cleanup: 8 scalar index loads -> 2x int4 vector loads.

static constexpr int EMBED_DIM    = 1024;
static constexpr int VEC_PER_ROW  = EMBED_DIM / 4;   // 256 float4 per row
static constexpr int ROWS_PER_CTA = 8;

static __device__ __forceinline__ float4 ldcg_f4(const float4* p) {
    float4 v;
    asm volatile("ld.global.cg.v4.f32 {%0,%1,%2,%3}, [%4];"
                 : "=f"(v.x), "=f"(v.y), "=f"(v.z), "=f"(v.w) : "l"(p));
    return v;
}

static __device__ __forceinline__ void stcs_f4(float4* p, float4 v) {
    asm volatile("st.global.cs.v4.f32 [%0], {%1,%2,%3,%4};"
                 :: "l"(p), "f"(v.x), "f"(v.y), "f"(v.z), "f"(v.w) : "memory");
}

__global__ __launch_bounds__(256, 4)
void embedding_gather_kernel(const int4* __restrict__ idx4,
                             const float4* __restrict__ emb,
                             float4* __restrict__ out)
{
    const int  base = blockIdx.x * ROWS_PER_CTA;
    const int  t    = threadIdx.x;

    // 8 indices via two 16B vector loads (one 32B sector, broadcast)
    const int4 i0 = idx4[blockIdx.x * 2 + 0];
    const int4 i1 = idx4[blockIdx.x * 2 + 1];
    const int  src[ROWS_PER_CTA] = { i0.x, i0.y, i0.z, i0.w,
                                     i1.x, i1.y, i1.z, i1.w };

    const float4* __restrict__ emb_lane = emb + t;

    // 8 independent gathers, front-batched (MLP=8), L2-only
    float4 v[ROWS_PER_CTA];
#pragma unroll
    for (int r = 0; r < ROWS_PER_CTA; r++)
        v[r] = ldcg_f4(emb_lane + (long long)src[r] * VEC_PER_ROW);

    // 8 coalesced streaming stores
    float4* __restrict__ out_base = out + (long long)base * VEC_PER_ROW + t;
#pragma unroll
    for (int r = 0; r < ROWS_PER_CTA; r++)
        stcs_f4(out_base + (long long)r * VEC_PER_ROW, v[r]);
}

extern "C" void kernel_launch(void* const* d_in, const int* in_sizes, int n_in,
                              void* d_out, int out_size)
{
    const int*   x   = (const int*)d_in[0];          // [4, 2048] int32 indices
    const float* emb = (const float*)d_in[1];        // [32000, 1024] fp32
    float*       out = (float*)d_out;                // [4, 2048, 1024] fp32

    const int n_rows = in_sizes[0];                  // 8192
    const int n_cta  = n_rows / ROWS_PER_CTA;        // 1024

    embedding_gather_kernel<<<n_cta, 256>>>(
        (const int4*)x, (const float4*)emb, (float4*)out);
}

// round 12
// speedup vs baseline: 1.0120x; 1.0120x over previous
#include <cuda_runtime.h>
#include <cuda_bf16.h>
#include <cstdint>

// Embedding gather: out[i, :] = embeddings[x[i], :]
// x: int32 [8192], embeddings: fp32 [32000, 1024], out: fp32 [8192, 1024]
//
// FINAL — measured-best configuration of the session (10.528us, best of 10
// benched variants spanning occupancy 1.6%-78%, MLP 1-40, LDG vs TMA vs
// hybrid paths, and 4 cache policies; all flat within +-10%).
//
// Why this is the roofline: the op moves 64MB of mandatory traffic through
// the LTS (32MB gathered table reads + 32MB output writes). The LTS chip
// service cap (~6300 B/cyc) is path-independent (LDG.cv == TMA, confirmed
// empirically by the hybrid experiment), and 10.5us == ~6.1 TB/s == ~90% of
// that ceiling. No further transformation reduces the mandatory traffic.
//
// Config: 1024 CTAs x 256 threads, 8 rows/CTA, front-batched MLP=8,
// ld.global.cg gathers (skip L1; gathered rows never re-hit),
// st.global.cs stores (evict-first; don't displace the table in L2).

static constexpr int EMBED_DIM    = 1024;
static constexpr int VEC_PER_ROW  = EMBED_DIM / 4;   // 256 float4 per row
static constexpr int ROWS_PER_CTA = 8;

static __device__ __forceinline__ float4 ldcg_f4(const float4* p) {
    float4 v;
    asm volatile("ld.global.cg.v4.f32 {%0,%1,%2,%3}, [%4];"
                 : "=f"(v.x), "=f"(v.y), "=f"(v.z), "=f"(v.w) : "l"(p));
    return v;
}

static __device__ __forceinline__ void stcs_f4(float4* p, float4 v) {
    asm volatile("st.global.cs.v4.f32 [%0], {%1,%2,%3,%4};"
                 :: "l"(p), "f"(v.x), "f"(v.y), "f"(v.z), "f"(v.w) : "memory");
}

__global__ __launch_bounds__(256, 4)
void embedding_gather_kernel(const int* __restrict__ idx,
                             const float4* __restrict__ emb,
                             float4* __restrict__ out)
{
    const int base = blockIdx.x * ROWS_PER_CTA;
    const int t    = threadIdx.x;

    // 8 index loads (one 32B sector, broadcast; L2-hot after first touch)
    long long src[ROWS_PER_CTA];
#pragma unroll
    for (int r = 0; r < ROWS_PER_CTA; r++)
        src[r] = (long long)idx[base + r];

    // 8 independent gathers, front-batched (MLP=8), L2-only
    float4 v[ROWS_PER_CTA];
#pragma unroll
    for (int r = 0; r < ROWS_PER_CTA; r++)
        v[r] = ldcg_f4(&emb[src[r] * VEC_PER_ROW + t]);

    // 8 coalesced streaming stores (evict-first: protect the table in L2)
#pragma unroll
    for (int r = 0; r < ROWS_PER_CTA; r++)
        stcs_f4(&out[(long long)(base + r) * VEC_PER_ROW + t], v[r]);
}

extern "C" void kernel_launch(void* const* d_in, const int* in_sizes, int n_in,
                              void* d_out, int out_size)
{
    const int*   x   = (const int*)d_in[0];          // [4, 2048] int32 indices
    const float* emb = (const float*)d_in[1];        // [32000, 1024] fp32
    float*       out = (float*)d_out;                // [4, 2048, 1024] fp32

    const int n_rows = in_sizes[0];                  // 8192
    const int n_cta  = n_rows / ROWS_PER_CTA;        // 1024

    embedding_gather_kernel<<<n_cta, 256>>>(
        x, (const float4*)emb, (float4*)out);
}

// round 13
// speedup vs baseline: 1.0500x; 1.0375x over previous
#include <cuda_runtime.h>
#include <cuda_bf16.h>
#include <cstdint>

// Embedding gather: out[i, :] = embeddings[x[i], :]
// x: int32 [8192], embeddings: fp32 [32000, 1024], out: fp32 [8192, 1024]
//
// Shape-sweep point: 4 rows/CTA, 2048 CTAs x 256 threads, MLP=4.
// (Measured: 1 row/8192 CTAs = 12.26us; 8 rows/1024 CTAs = 10.53us.
//  This tests the intermediate: smoother CTA interleave across LTS slices,
//  shorter load batches, most of the MLP benefit already present at 4.)
// Cache policy = best known: ld.global.cg gathers + st.global.cs stores.

static constexpr int EMBED_DIM    = 1024;
static constexpr int VEC_PER_ROW  = EMBED_DIM / 4;   // 256 float4 per row
static constexpr int ROWS_PER_CTA = 4;

static __device__ __forceinline__ float4 ldcg_f4(const float4* p) {
    float4 v;
    asm volatile("ld.global.cg.v4.f32 {%0,%1,%2,%3}, [%4];"
                 : "=f"(v.x), "=f"(v.y), "=f"(v.z), "=f"(v.w) : "l"(p));
    return v;
}

static __device__ __forceinline__ void stcs_f4(float4* p, float4 v) {
    asm volatile("st.global.cs.v4.f32 [%0], {%1,%2,%3,%4};"
                 :: "l"(p), "f"(v.x), "f"(v.y), "f"(v.z), "f"(v.w) : "memory");
}

__global__ __launch_bounds__(256, 8)
void embedding_gather_kernel(const int* __restrict__ idx,
                             const float4* __restrict__ emb,
                             float4* __restrict__ out)
{
    const int base = blockIdx.x * ROWS_PER_CTA;
    const int t    = threadIdx.x;

    // 4 index loads (one 16B sector, broadcast)
    long long src[ROWS_PER_CTA];
#pragma unroll
    for (int r = 0; r < ROWS_PER_CTA; r++)
        src[r] = (long long)idx[base + r];

    // 4 independent gathers, front-batched (MLP=4), L2-only
    float4 v[ROWS_PER_CTA];
#pragma unroll
    for (int r = 0; r < ROWS_PER_CTA; r++)
        v[r] = ldcg_f4(&emb[src[r] * VEC_PER_ROW + t]);

    // 4 coalesced streaming stores
#pragma unroll
    for (int r = 0; r < ROWS_PER_CTA; r++)
        stcs_f4(&out[(long long)(base + r) * VEC_PER_ROW + t], v[r]);
}

extern "C" void kernel_launch(void* const* d_in, const int* in_sizes, int n_in,
                              void* d_out, int out_size)
{
    const int*   x   = (const int*)d_in[0];          // [4, 2048] int32 indices
    const float* emb = (const float*)d_in[1];        // [32000, 1024] fp32
    float*       out = (float*)d_out;                // [4, 2048, 1024] fp32

    const int n_rows = in_sizes[0];                  // 8192
    const int n_cta  = n_rows / ROWS_PER_CTA;        // 2048

    embedding_gather_kernel<<<n_cta, 256>>>(
        x, (const float4*)emb, (float4*)out);
}

// round 14
// speedup vs baseline: 1.0533x; 1.0031x over previous
#include <cuda_runtime.h>
#include <cuda_bf16.h>
#include <cstdint>

// Embedding gather: out[i, :] = embeddings[x[i], :]
// x: int32 [8192], embeddings: fp32 [32000, 1024], out: fp32 [8192, 1024]
//
// Best shape (measured sweep): 4 rows/CTA, 2048 CTAs x 256 threads, MLP=4,
// 24 regs -> 8 CTAs/SM (full 2048 threads). The winning tradeoff is
// (resident warps x per-thread MLP); ROWS=4 maximizes it.
//
// This round: trim the issue path inside the winning shape —
//   - indices via one int4 vector load (4 LDGs -> 1)
//   - all offset math in 32-bit (row offsets < 2^31; float4 indexing
//     supplies the x16 byte scale), killing wide IMAD chains
//   - ld.global.cg gathers + st.global.cs stores (best measured policy)

static constexpr int EMBED_DIM    = 1024;
static constexpr int VEC_PER_ROW  = EMBED_DIM / 4;   // 256 float4 per row
static constexpr int ROWS_PER_CTA = 4;

static __device__ __forceinline__ float4 ldcg_f4(const float4* p) {
    float4 v;
    asm volatile("ld.global.cg.v4.f32 {%0,%1,%2,%3}, [%4];"
                 : "=f"(v.x), "=f"(v.y), "=f"(v.z), "=f"(v.w) : "l"(p));
    return v;
}

static __device__ __forceinline__ void stcs_f4(float4* p, float4 v) {
    asm volatile("st.global.cs.v4.f32 [%0], {%1,%2,%3,%4};"
                 :: "l"(p), "f"(v.x), "f"(v.y), "f"(v.z), "f"(v.w) : "memory");
}

__global__ __launch_bounds__(256, 8)
void embedding_gather_kernel(const int4* __restrict__ idx4,
                             const float4* __restrict__ emb,
                             float4* __restrict__ out)
{
    const unsigned t = threadIdx.x;

    // 4 indices in one 16B load (broadcast within CTA)
    const int4 i4 = idx4[blockIdx.x];

    // 32-bit element offsets: max 31999*256 + 255 < 2^31
    const unsigned off0 = (unsigned)i4.x * VEC_PER_ROW + t;
    const unsigned off1 = (unsigned)i4.y * VEC_PER_ROW + t;
    const unsigned off2 = (unsigned)i4.z * VEC_PER_ROW + t;
    const unsigned off3 = (unsigned)i4.w * VEC_PER_ROW + t;

    // 4 independent gathers, front-batched (MLP=4), L2-only
    float4 v0 = ldcg_f4(emb + off0);
    float4 v1 = ldcg_f4(emb + off1);
    float4 v2 = ldcg_f4(emb + off2);
    float4 v3 = ldcg_f4(emb + off3);

    // 4 coalesced streaming stores (out offsets also < 2^31: 8192*256)
    float4* o = out + (unsigned)blockIdx.x * (ROWS_PER_CTA * VEC_PER_ROW) + t;
    stcs_f4(o + 0 * VEC_PER_ROW, v0);
    stcs_f4(o + 1 * VEC_PER_ROW, v1);
    stcs_f4(o + 2 * VEC_PER_ROW, v2);
    stcs_f4(o + 3 * VEC_PER_ROW, v3);
}

extern "C" void kernel_launch(void* const* d_in, const int* in_sizes, int n_in,
                              void* d_out, int out_size)
{
    const int*   x   = (const int*)d_in[0];          // [4, 2048] int32 indices
    const float* emb = (const float*)d_in[1];        // [32000, 1024] fp32
    float*       out = (float*)d_out;                // [4, 2048, 1024] fp32

    const int n_rows = in_sizes[0];                  // 8192
    const int n_cta  = n_rows / ROWS_PER_CTA;        // 2048

    embedding_gather_kernel<<<n_cta, 256>>>(
        (const int4*)x, (const float4*)emb, (float4*)out);
}